// round 2
// baseline (speedup 1.0000x reference)
#include <cuda_runtime.h>
#include <math.h>

#define FEAT   128
#define NN     512          // T + taus
#define BATCH  4
#define NSAMP  5
#define E_CNT  97920        // edges with sink row > 256
#define BASE0  32896        // 256*257/2

// Scratch (static device globals: no allocation allowed)
__device__ float g_A[BATCH * NN * FEAT];   // nodes @ W1_top
__device__ float g_Bm[BATCH * NN * FEAT];  // nodes @ W1_bot
__device__ unsigned long long g_best[BATCH * NSAMP];

// ---------------------------------------------------------------------------
// JAX Threefry-2x32, key = (0, 42), PARTITIONABLE counter scheme (default
// since jax 0.4.36): per-element 64-bit counter j (hi=0 here since
// size < 2^32); bits[j] = v0 ^ v1 of threefry2x32((0,42), (0, j)).
// ---------------------------------------------------------------------------
__device__ __forceinline__ unsigned rotl32(unsigned v, int s) {
    return (v << s) | (v >> (32 - s));
}

__device__ __forceinline__ unsigned threefry_bits(unsigned j) {
    const unsigned ks0 = 0u;
    const unsigned ks1 = 42u;
    const unsigned ks2 = 0x1BD11BDAu ^ 0u ^ 42u;
    unsigned x0 = 0u + ks0;        // counts_hi + ks0
    unsigned x1 = j  + ks1;        // counts_lo + ks1
#define RND(r) { x0 += x1; x1 = rotl32(x1, (r)); x1 ^= x0; }
    RND(13) RND(15) RND(26) RND(6)
    x0 += ks1; x1 += ks2 + 1u;
    RND(17) RND(29) RND(16) RND(24)
    x0 += ks2; x1 += ks0 + 2u;
    RND(13) RND(15) RND(26) RND(6)
    x0 += ks0; x1 += ks1 + 3u;
    RND(17) RND(29) RND(16) RND(24)
    x0 += ks1; x1 += ks2 + 4u;
    RND(13) RND(15) RND(26) RND(6)
    x0 += ks2; x1 += ks0 + 5u;
#undef RND
    return x0 ^ x1;                // 32-bit fold of the two output words
}

// gumbel = -log(-log(u)) with u = max(tiny, uniform-from-bits)
__device__ __forceinline__ float gumbel_from_bits(unsigned bits) {
    unsigned m = bits >> 9;
    float u;
    if (m == 0u) u = 1.17549435e-38f;
    else         u = __uint_as_float(0x3F800000u | m) - 1.0f;
    return -logf(-logf(u));
}

// edge e -> (row r, col c): e + BASE0 = r(r-1)/2 + c, 257 <= r <= 511, c < r
__device__ __forceinline__ void decode_edge(int e, int &r, int &c) {
    int t = e + BASE0;
    int rr = (int)((1.0f + sqrtf(8.0f * (float)t + 1.0f)) * 0.5f);
    while (rr * (rr - 1) / 2 > t) --rr;
    while ((rr + 1) * rr / 2 <= t) ++rr;
    r = rr;
    c = t - rr * (rr - 1) / 2;
}

__device__ __forceinline__ float warp_sum(float v) {
    v += __shfl_xor_sync(0xffffffffu, v, 16);
    v += __shfl_xor_sync(0xffffffffu, v, 8);
    v += __shfl_xor_sync(0xffffffffu, v, 4);
    v += __shfl_xor_sync(0xffffffffu, v, 2);
    v += __shfl_xor_sync(0xffffffffu, v, 1);
    return v;
}

// ---------------------------------------------------------------------------
// Kernel 0: zero output + reset argmax slots
// ---------------------------------------------------------------------------
__global__ void init_kernel(float4 *out) {
    int i = blockIdx.x * blockDim.x + threadIdx.x;
    if (i < (BATCH * NN * NN) / 4) out[i] = make_float4(0.f, 0.f, 0.f, 0.f);
    if (blockIdx.x == 0 && threadIdx.x < BATCH * NSAMP) g_best[threadIdx.x] = 0ull;
}

// ---------------------------------------------------------------------------
// Kernel 1: per-node layer-1 partials.
//   g_A[b,n,f] = sum_i nodes[b,n,i] * W1[i, f]
//   g_Bm[b,n,f]= sum_i nodes[b,n,i] * W1[128+i, f]
// ---------------------------------------------------------------------------
__global__ void precompute_kernel(const float *__restrict__ nodes,
                                  const float *__restrict__ W1) {
    int bn = blockIdx.x;          // 0 .. B*NN-1
    int f  = threadIdx.x;         // 0 .. 127
    __shared__ float sn[FEAT];
    sn[f] = nodes[bn * FEAT + f];
    __syncthreads();
    float a = 0.f, bb = 0.f;
#pragma unroll 8
    for (int i = 0; i < FEAT; ++i) {
        float v = sn[i];
        a  += v * W1[i * FEAT + f];
        bb += v * W1[(i + FEAT) * FEAT + f];
    }
    g_A[bn * FEAT + f]  = a;
    g_Bm[bn * FEAT + f] = bb;
}

// ---------------------------------------------------------------------------
// Kernel 2: per-edge MLP -> logit -> gumbel scores -> per-(b,s) argmax merge.
// One warp per edge (grid-stride). Features mapped f = lane*4 + k (float4).
// W2 staged in dynamic shared (64 KB).
// ---------------------------------------------------------------------------
extern __shared__ float sW2[];

__global__ void __launch_bounds__(256)
main_kernel(const float *__restrict__ b1,  const float *__restrict__ g1,
            const float *__restrict__ be1, const float *__restrict__ W2,
            const float *__restrict__ b2,  const float *__restrict__ g2,
            const float *__restrict__ be2, const float *__restrict__ W3,
            const float *__restrict__ b3) {
    const int tid  = threadIdx.x;
    const int lane = tid & 31;
    const int warp = tid >> 5;
    const int b    = blockIdx.y;

    // stage W2 (row-major [in][out], 128x128 f32)
    {
        const float4 *src = (const float4 *)W2;
        float4 *dst = (float4 *)sW2;
        for (int i = tid; i < FEAT * FEAT / 4; i += blockDim.x) dst[i] = src[i];
    }

    // per-lane parameter slices (f = lane*4 + k)
    float c_b1[4], c_g1[4], c_be1[4], c_b2[4], c_g2[4], c_be2[4], c_W3[4];
#pragma unroll
    for (int k = 0; k < 4; ++k) {
        int f = lane * 4 + k;
        c_b1[k] = b1[f];  c_g1[k] = g1[f];  c_be1[k] = be1[f];
        c_b2[k] = b2[f];  c_g2[k] = g2[f];  c_be2[k] = be2[f];
        c_W3[k] = W3[f];
    }
    const float c_b3 = b3[0];
    __syncthreads();

    // per-lane running best for sample s = lane (lanes 0..4 meaningful)
    float    bestS = -__int_as_float(0x7f800000);  // -inf
    unsigned bestE = 0u;

    const float *Abase = g_A  + b * NN * FEAT;
    const float *Bbase = g_Bm + b * NN * FEAT;

    const int warpId     = blockIdx.x * (blockDim.x >> 5) + warp;
    const int warpStride = gridDim.x * (blockDim.x >> 5);

    for (int e = warpId; e < E_CNT; e += warpStride) {
        int r, c;
        decode_edge(e, r, c);

        // ---- layer 1: h = relu(A[sink] + Bm[src] + b1), then LN ----
        float4 av = *(const float4 *)(Abase + r * FEAT + lane * 4);
        float4 bv = *(const float4 *)(Bbase + c * FEAT + lane * 4);
        float h[4];
        h[0] = fmaxf(av.x + bv.x + c_b1[0], 0.f);
        h[1] = fmaxf(av.y + bv.y + c_b1[1], 0.f);
        h[2] = fmaxf(av.z + bv.z + c_b1[2], 0.f);
        h[3] = fmaxf(av.w + bv.w + c_b1[3], 0.f);

        float mu = warp_sum(h[0] + h[1] + h[2] + h[3]) * (1.f / 128.f);
        float d0 = h[0] - mu, d1 = h[1] - mu, d2 = h[2] - mu, d3 = h[3] - mu;
        float var = warp_sum(d0 * d0 + d1 * d1 + d2 * d2 + d3 * d3) * (1.f / 128.f);
        float inv = rsqrtf(var + 1e-5f);
        float x0v = d0 * inv * c_g1[0] + c_be1[0];
        float x1v = d1 * inv * c_g1[1] + c_be1[1];
        float x2v = d2 * inv * c_g1[2] + c_be1[2];
        float x3v = d3 * inv * c_g1[3] + c_be1[3];

        // ---- layer 2: acc[o] = sum_i x[i] * W2[i,o], o = lane*4+k ----
        float a0 = 0.f, a1 = 0.f, a2 = 0.f, a3 = 0.f;
#pragma unroll 4
        for (int src = 0; src < 32; ++src) {
            float v0 = __shfl_sync(0xffffffffu, x0v, src);
            float v1 = __shfl_sync(0xffffffffu, x1v, src);
            float v2 = __shfl_sync(0xffffffffu, x2v, src);
            float v3 = __shfl_sync(0xffffffffu, x3v, src);
            const float4 *row0 = (const float4 *)(sW2 + (src * 4 + 0) * FEAT);
            const float4 *row1 = (const float4 *)(sW2 + (src * 4 + 1) * FEAT);
            const float4 *row2 = (const float4 *)(sW2 + (src * 4 + 2) * FEAT);
            const float4 *row3 = (const float4 *)(sW2 + (src * 4 + 3) * FEAT);
            float4 w;
            w = row0[lane]; a0 += v0 * w.x; a1 += v0 * w.y; a2 += v0 * w.z; a3 += v0 * w.w;
            w = row1[lane]; a0 += v1 * w.x; a1 += v1 * w.y; a2 += v1 * w.z; a3 += v1 * w.w;
            w = row2[lane]; a0 += v2 * w.x; a1 += v2 * w.y; a2 += v2 * w.z; a3 += v2 * w.w;
            w = row3[lane]; a0 += v3 * w.x; a1 += v3 * w.y; a2 += v3 * w.z; a3 += v3 * w.w;
        }
        // relu + LN
        h[0] = fmaxf(a0 + c_b2[0], 0.f);
        h[1] = fmaxf(a1 + c_b2[1], 0.f);
        h[2] = fmaxf(a2 + c_b2[2], 0.f);
        h[3] = fmaxf(a3 + c_b2[3], 0.f);
        mu = warp_sum(h[0] + h[1] + h[2] + h[3]) * (1.f / 128.f);
        d0 = h[0] - mu; d1 = h[1] - mu; d2 = h[2] - mu; d3 = h[3] - mu;
        var = warp_sum(d0 * d0 + d1 * d1 + d2 * d2 + d3 * d3) * (1.f / 128.f);
        inv = rsqrtf(var + 1e-5f);
        float y0 = d0 * inv * c_g2[0] + c_be2[0];
        float y1 = d1 * inv * c_g2[1] + c_be2[1];
        float y2 = d2 * inv * c_g2[2] + c_be2[2];
        float y3 = d3 * inv * c_g2[3] + c_be2[3];

        // ---- layer 3: logit ----
        float logit = warp_sum(y0 * c_W3[0] + y1 * c_W3[1] + y2 * c_W3[2] + y3 * c_W3[3]) + c_b3;

        // ---- gumbel scores for samples s = lane (lanes 0..4) ----
        if (lane < NSAMP) {
            unsigned j = (unsigned)((b * NSAMP + lane) * E_CNT + e);
            float sc = logit + gumbel_from_bits(threefry_bits(j));
            if (sc > bestS) { bestS = sc; bestE = (unsigned)e; }
        }
    }

    // merge into global per-(b,s) argmax: ordered-float pack, smaller e wins ties
    if (lane < NSAMP) {
        unsigned bu = __float_as_uint(bestS);
        bu = (bu & 0x80000000u) ? ~bu : (bu | 0x80000000u);
        unsigned long long packed =
            ((unsigned long long)bu << 32) | (unsigned long long)(0x7FFFFFFFu - bestE);
        atomicMax(&g_best[b * NSAMP + lane], packed);
    }
}

// ---------------------------------------------------------------------------
// Kernel 3: scatter winners
// ---------------------------------------------------------------------------
__global__ void finalize_kernel(float *out) {
    int t = threadIdx.x;
    if (t >= BATCH * NSAMP) return;
    unsigned long long p = g_best[t];
    unsigned e = 0x7FFFFFFFu - (unsigned)(p & 0xFFFFFFFFull);
    int b = t / NSAMP;
    int r, c;
    decode_edge((int)e, r, c);
    out[b * NN * NN + r * NN + c] = 1.0f;
}

// ---------------------------------------------------------------------------
extern "C" void kernel_launch(void *const *d_in, const int *in_sizes, int n_in,
                              void *d_out, int out_size) {
    const float *nodes = (const float *)d_in[0];
    const float *W1    = (const float *)d_in[1];
    const float *b1    = (const float *)d_in[2];
    const float *g1    = (const float *)d_in[3];
    const float *be1   = (const float *)d_in[4];
    const float *W2    = (const float *)d_in[5];
    const float *b2    = (const float *)d_in[6];
    const float *g2    = (const float *)d_in[7];
    const float *be2   = (const float *)d_in[8];
    const float *W3    = (const float *)d_in[9];
    const float *b3    = (const float *)d_in[10];

    cudaFuncSetAttribute(main_kernel, cudaFuncAttributeMaxDynamicSharedMemorySize,
                         FEAT * FEAT * (int)sizeof(float));

    init_kernel<<<1024, 256>>>((float4 *)d_out);
    precompute_kernel<<<BATCH * NN, FEAT>>>(nodes, W1);
    main_kernel<<<dim3(333, BATCH), 256, FEAT * FEAT * sizeof(float)>>>(
        b1, g1, be1, W2, b2, g2, be2, W3, b3);
    finalize_kernel<<<1, 32>>>((float *)d_out);
}

// round 3
// speedup vs baseline: 1.6396x; 1.6396x over previous
#include <cuda_runtime.h>
#include <math.h>

#define FEAT   128
#define NN     512          // T + taus
#define BATCH  4
#define NSAMP  5
#define E_CNT  97920        // edges with sink row > 256
#define BASE0  32896        // 256*257/2
#define EPB    8            // edges per warp batch (E_CNT = 12240 * 8 exactly)
#define NWARP  6            // warps per block
#define NTHR   (NWARP * 32)
#define W2T_STRIDE 132      // floats per transposed-W2 row (conflict-free, 16B-aligned)
#define NTASK  (E_CNT / EPB)   // 12240

// Scratch (static device globals: no allocation allowed)
__device__ float g_A[BATCH * NN * FEAT];   // nodes @ W1_top
__device__ float g_Bm[BATCH * NN * FEAT];  // nodes @ W1_bot
__device__ unsigned long long g_best[BATCH * NSAMP];

// ---------------------------------------------------------------------------
// JAX Threefry-2x32, key (0,42), partitionable scheme: bits[j] = v0^v1 of
// threefry2x32((0,42), (0, j)).
// ---------------------------------------------------------------------------
__device__ __forceinline__ unsigned rotl32(unsigned v, int s) {
    return (v << s) | (v >> (32 - s));
}

__device__ __forceinline__ unsigned threefry_bits(unsigned j) {
    const unsigned ks0 = 0u;
    const unsigned ks1 = 42u;
    const unsigned ks2 = 0x1BD11BDAu ^ 0u ^ 42u;
    unsigned x0 = 0u + ks0;
    unsigned x1 = j  + ks1;
#define RND(r) { x0 += x1; x1 = rotl32(x1, (r)); x1 ^= x0; }
    RND(13) RND(15) RND(26) RND(6)
    x0 += ks1; x1 += ks2 + 1u;
    RND(17) RND(29) RND(16) RND(24)
    x0 += ks2; x1 += ks0 + 2u;
    RND(13) RND(15) RND(26) RND(6)
    x0 += ks0; x1 += ks1 + 3u;
    RND(17) RND(29) RND(16) RND(24)
    x0 += ks1; x1 += ks2 + 4u;
    RND(13) RND(15) RND(26) RND(6)
    x0 += ks2; x1 += ks0 + 5u;
#undef RND
    return x0 ^ x1;
}

__device__ __forceinline__ float gumbel_from_bits(unsigned bits) {
    unsigned m = bits >> 9;
    float u;
    if (m == 0u) u = 1.17549435e-38f;
    else         u = __uint_as_float(0x3F800000u | m) - 1.0f;
    return -logf(-logf(u));
}

// edge e -> (row r, col c): e + BASE0 = r(r-1)/2 + c, 257 <= r <= 511, c < r
__device__ __forceinline__ void decode_edge(int e, int &r, int &c) {
    int t = e + BASE0;
    int rr = (int)((1.0f + sqrtf(8.0f * (float)t + 1.0f)) * 0.5f);
    while (rr * (rr - 1) / 2 > t) --rr;
    while ((rr + 1) * rr / 2 <= t) ++rr;
    r = rr;
    c = t - rr * (rr - 1) / 2;
}

__device__ __forceinline__ float warp_sum(float v) {
    v += __shfl_xor_sync(0xffffffffu, v, 16);
    v += __shfl_xor_sync(0xffffffffu, v, 8);
    v += __shfl_xor_sync(0xffffffffu, v, 4);
    v += __shfl_xor_sync(0xffffffffu, v, 2);
    v += __shfl_xor_sync(0xffffffffu, v, 1);
    return v;
}

// packed fp32x2 fused multiply-add (Blackwell FFMA2)
__device__ __forceinline__ unsigned long long fma2(unsigned long long a,
                                                   unsigned long long b,
                                                   unsigned long long c) {
    unsigned long long d;
    asm("fma.rn.f32x2 %0, %1, %2, %3;" : "=l"(d) : "l"(a), "l"(b), "l"(c));
    return d;
}

// ---------------------------------------------------------------------------
// Kernel 0: zero output + reset argmax slots
// ---------------------------------------------------------------------------
__global__ void init_kernel(float4 *out) {
    int i = blockIdx.x * blockDim.x + threadIdx.x;
    if (i < (BATCH * NN * NN) / 4) out[i] = make_float4(0.f, 0.f, 0.f, 0.f);
    if (blockIdx.x == 0 && threadIdx.x < BATCH * NSAMP) g_best[threadIdx.x] = 0ull;
}

// ---------------------------------------------------------------------------
// Kernel 1: per-node layer-1 partials. 8 nodes per block (W1 reuse).
// ---------------------------------------------------------------------------
__global__ void precompute_kernel(const float *__restrict__ nodes,
                                  const float *__restrict__ W1) {
    int f  = threadIdx.x;              // 0..127
    int nb = blockIdx.x * 8;           // node base
    __shared__ float sn[8][FEAT];
#pragma unroll
    for (int k = 0; k < 8; ++k) sn[k][f] = nodes[(nb + k) * FEAT + f];
    __syncthreads();
    float a[8], bb[8];
#pragma unroll
    for (int k = 0; k < 8; ++k) { a[k] = 0.f; bb[k] = 0.f; }
    for (int i = 0; i < FEAT; ++i) {
        float wt = W1[i * FEAT + f];
        float wb = W1[(i + FEAT) * FEAT + f];
#pragma unroll
        for (int k = 0; k < 8; ++k) {
            a[k]  += sn[k][i] * wt;
            bb[k] += sn[k][i] * wb;
        }
    }
#pragma unroll
    for (int k = 0; k < 8; ++k) {
        g_A[(nb + k) * FEAT + f]  = a[k];
        g_Bm[(nb + k) * FEAT + f] = bb[k];
    }
}

// ---------------------------------------------------------------------------
// Kernel 2: per-edge MLP -> logit -> gumbel -> per-(b,s) argmax merge.
// Each warp processes EPB=8 edges per batch:
//   Phase A: layer-1 + LN per edge (lane owns features lane*4+k), store x to sX
//   Phase B: layer-2 matvec via packed f32x2 FMAs; W2 transposed in smem,
//            lane owns outputs {kk*32+lane}; x read via LDS broadcast
//   Phase C: LN + W3 + gumbel per edge
// ---------------------------------------------------------------------------
extern __shared__ float smem_dyn[];

__global__ void __launch_bounds__(NTHR, 2)
main_kernel(const float *__restrict__ b1,  const float *__restrict__ g1,
            const float *__restrict__ be1, const float *__restrict__ W2,
            const float *__restrict__ b2,  const float *__restrict__ g2,
            const float *__restrict__ be2, const float *__restrict__ W3,
            const float *__restrict__ b3) {
    const int tid  = threadIdx.x;
    const int lane = tid & 31;
    const int warp = tid >> 5;
    const int b    = blockIdx.y;

    float *sW2T = smem_dyn;                              // [128][W2T_STRIDE]
    float *sX   = smem_dyn + FEAT * W2T_STRIDE + warp * (EPB * FEAT);

    // Stage W2 transposed: sW2T[o*stride + i] = W2[i*128 + o]
    for (int idx = tid; idx < FEAT * FEAT; idx += NTHR) {
        int i = idx >> 7;
        int o = idx & 127;
        sW2T[o * W2T_STRIDE + i] = W2[idx];
    }

    // Phase-A params: feature f = lane*4+k
    float c_b1[4], c_g1[4], c_be1[4];
    // Phase-C params: output o = kk*32+lane
    float c_b2[4], c_g2[4], c_be2[4], c_W3[4];
#pragma unroll
    for (int k = 0; k < 4; ++k) {
        int fA = lane * 4 + k;
        c_b1[k] = b1[fA];  c_g1[k] = g1[fA];  c_be1[k] = be1[fA];
        int fC = k * 32 + lane;
        c_b2[k] = b2[fC];  c_g2[k] = g2[fC];  c_be2[k] = be2[fC];
        c_W3[k] = W3[fC];
    }
    const float c_b3 = b3[0];
    __syncthreads();

    float    bestS = -__int_as_float(0x7f800000);  // -inf
    unsigned bestE = 0u;

    const float *Abase = g_A  + b * NN * FEAT;
    const float *Bbase = g_Bm + b * NN * FEAT;

    const int warpGlobal = blockIdx.x * NWARP + warp;
    const int totalWarps = gridDim.x * NWARP;

    for (int task = warpGlobal; task < NTASK; task += totalWarps) {
        const int ebase = task * EPB;

        // ---- Phase A: layer-1 + LN, write x to sX ----
#pragma unroll
        for (int k = 0; k < EPB; ++k) {
            int r, c;
            decode_edge(ebase + k, r, c);
            float4 av = *(const float4 *)(Abase + r * FEAT + lane * 4);
            float4 bv = *(const float4 *)(Bbase + c * FEAT + lane * 4);
            float h0 = fmaxf(av.x + bv.x + c_b1[0], 0.f);
            float h1 = fmaxf(av.y + bv.y + c_b1[1], 0.f);
            float h2 = fmaxf(av.z + bv.z + c_b1[2], 0.f);
            float h3 = fmaxf(av.w + bv.w + c_b1[3], 0.f);
            float mu = warp_sum(h0 + h1 + h2 + h3) * (1.f / 128.f);
            float d0 = h0 - mu, d1 = h1 - mu, d2 = h2 - mu, d3 = h3 - mu;
            float var = warp_sum(d0 * d0 + d1 * d1 + d2 * d2 + d3 * d3) * (1.f / 128.f);
            float inv = rsqrtf(var + 1e-5f);
            float4 xv;
            xv.x = d0 * inv * c_g1[0] + c_be1[0];
            xv.y = d1 * inv * c_g1[1] + c_be1[1];
            xv.z = d2 * inv * c_g1[2] + c_be1[2];
            xv.w = d3 * inv * c_g1[3] + c_be1[3];
            *(float4 *)(sX + k * FEAT + lane * 4) = xv;
        }
        __syncwarp();

        // ---- Phase B: layer-2 matvec, packed f32x2 ----
        unsigned long long acc[EPB][4];
#pragma unroll
        for (int e = 0; e < EPB; ++e)
#pragma unroll
            for (int kk = 0; kk < 4; ++kk) acc[e][kk] = 0ull;

        const float *wrow0 = sW2T + (0 * 32 + lane) * W2T_STRIDE;
        const float *wrow1 = sW2T + (1 * 32 + lane) * W2T_STRIDE;
        const float *wrow2 = sW2T + (2 * 32 + lane) * W2T_STRIDE;
        const float *wrow3 = sW2T + (3 * 32 + lane) * W2T_STRIDE;

        for (int g = 0; g < 32; ++g) {
            const int go = g * 4;
            ulonglong2 wv0 = *(const ulonglong2 *)(wrow0 + go);
            ulonglong2 wv1 = *(const ulonglong2 *)(wrow1 + go);
            ulonglong2 wv2 = *(const ulonglong2 *)(wrow2 + go);
            ulonglong2 wv3 = *(const ulonglong2 *)(wrow3 + go);
#pragma unroll
            for (int e = 0; e < EPB; ++e) {
                ulonglong2 xv = *(const ulonglong2 *)(sX + e * FEAT + go);
                acc[e][0] = fma2(xv.x, wv0.x, acc[e][0]);
                acc[e][0] = fma2(xv.y, wv0.y, acc[e][0]);
                acc[e][1] = fma2(xv.x, wv1.x, acc[e][1]);
                acc[e][1] = fma2(xv.y, wv1.y, acc[e][1]);
                acc[e][2] = fma2(xv.x, wv2.x, acc[e][2]);
                acc[e][2] = fma2(xv.y, wv2.y, acc[e][2]);
                acc[e][3] = fma2(xv.x, wv3.x, acc[e][3]);
                acc[e][3] = fma2(xv.y, wv3.y, acc[e][3]);
            }
        }

        // ---- Phase C: LN + logit + gumbel per edge ----
#pragma unroll
        for (int e = 0; e < EPB; ++e) {
            float h[4];
#pragma unroll
            for (int kk = 0; kk < 4; ++kk) {
                float lo, hi;
                asm("mov.b64 {%0,%1}, %2;" : "=f"(lo), "=f"(hi) : "l"(acc[e][kk]));
                h[kk] = fmaxf(lo + hi + c_b2[kk], 0.f);
            }
            float mu = warp_sum(h[0] + h[1] + h[2] + h[3]) * (1.f / 128.f);
            float d0 = h[0] - mu, d1 = h[1] - mu, d2 = h[2] - mu, d3 = h[3] - mu;
            float var = warp_sum(d0 * d0 + d1 * d1 + d2 * d2 + d3 * d3) * (1.f / 128.f);
            float inv = rsqrtf(var + 1e-5f);
            float y0 = d0 * inv * c_g2[0] + c_be2[0];
            float y1 = d1 * inv * c_g2[1] + c_be2[1];
            float y2 = d2 * inv * c_g2[2] + c_be2[2];
            float y3 = d3 * inv * c_g2[3] + c_be2[3];
            float logit = warp_sum(y0 * c_W3[0] + y1 * c_W3[1] +
                                   y2 * c_W3[2] + y3 * c_W3[3]) + c_b3;

            if (lane < NSAMP) {
                unsigned j = (unsigned)((b * NSAMP + lane) * E_CNT + (ebase + e));
                float sc = logit + gumbel_from_bits(threefry_bits(j));
                if (sc > bestS) { bestS = sc; bestE = (unsigned)(ebase + e); }
            }
        }
        __syncwarp();
    }

    // merge into global per-(b,s) argmax: ordered-float pack, smaller e wins ties
    if (lane < NSAMP) {
        unsigned bu = __float_as_uint(bestS);
        bu = (bu & 0x80000000u) ? ~bu : (bu | 0x80000000u);
        unsigned long long packed =
            ((unsigned long long)bu << 32) | (unsigned long long)(0x7FFFFFFFu - bestE);
        atomicMax(&g_best[b * NSAMP + lane], packed);
    }
}

// ---------------------------------------------------------------------------
// Kernel 3: scatter winners
// ---------------------------------------------------------------------------
__global__ void finalize_kernel(float *out) {
    int t = threadIdx.x;
    if (t >= BATCH * NSAMP) return;
    unsigned long long p = g_best[t];
    unsigned e = 0x7FFFFFFFu - (unsigned)(p & 0xFFFFFFFFull);
    int b = t / NSAMP;
    int r, c;
    decode_edge((int)e, r, c);
    out[b * NN * NN + r * NN + c] = 1.0f;
}

// ---------------------------------------------------------------------------
extern "C" void kernel_launch(void *const *d_in, const int *in_sizes, int n_in,
                              void *d_out, int out_size) {
    const float *nodes = (const float *)d_in[0];
    const float *W1    = (const float *)d_in[1];
    const float *b1    = (const float *)d_in[2];
    const float *g1    = (const float *)d_in[3];
    const float *be1   = (const float *)d_in[4];
    const float *W2    = (const float *)d_in[5];
    const float *b2    = (const float *)d_in[6];
    const float *g2    = (const float *)d_in[7];
    const float *be2   = (const float *)d_in[8];
    const float *W3    = (const float *)d_in[9];
    const float *b3    = (const float *)d_in[10];

    const int smem_bytes = (FEAT * W2T_STRIDE + NWARP * EPB * FEAT) * (int)sizeof(float);
    cudaFuncSetAttribute(main_kernel, cudaFuncAttributeMaxDynamicSharedMemorySize,
                         smem_bytes);

    init_kernel<<<1024, 256>>>((float4 *)d_out);
    precompute_kernel<<<BATCH * NN / 8, FEAT>>>(nodes, W1);
    main_kernel<<<dim3(74, BATCH), NTHR, smem_bytes>>>(
        b1, g1, be1, W2, b2, g2, be2, W3, b3);
    finalize_kernel<<<1, 32>>>((float *)d_out);
}

// round 5
// speedup vs baseline: 2.5325x; 1.5445x over previous
#include <cuda_runtime.h>
#include <cuda_bf16.h>
#include <math.h>
#include <stdint.h>

#define FEAT   128
#define NN     512
#define BATCH  4
#define NSAMP  5
#define E_CNT  97920
#define BASE0  32896
#define TILE_M 128
#define NTILE  (E_CNT / TILE_M)     // 765
#define DELTA  0.125f
#define MAXC   128
#define XS     68                   // word stride of bf16 tiles (conflict-free)
#define SMEM_X_BYTES (128 * XS * 4) // 34816
#define SMEM_MAIN (2 * SMEM_X_BYTES)

// ---------------------------------------------------------------------------
// Scratch (static device globals: no allocation allowed)
// ---------------------------------------------------------------------------
__device__ float    g_A[BATCH * NN * FEAT];
__device__ float    g_Bm[BATCH * NN * FEAT];
__device__ float    g_scores[BATCH * NSAMP * E_CNT];   // 7.8 MB
__device__ unsigned g_bestu[BATCH * NSAMP];            // flipped-float approx max
__device__ int      g_winner[BATCH * NSAMP];

// ---------------------------------------------------------------------------
// helpers
// ---------------------------------------------------------------------------
__device__ __forceinline__ unsigned flipf(float f) {
    unsigned u = __float_as_uint(f);
    return (u & 0x80000000u) ? ~u : (u | 0x80000000u);
}
__device__ __forceinline__ float unflipf(unsigned u) {
    return __uint_as_float((u & 0x80000000u) ? (u & 0x7FFFFFFFu) : ~u);
}
__device__ __forceinline__ unsigned rotl32(unsigned v, int s) {
    return (v << s) | (v >> (32 - s));
}
// JAX Threefry-2x32, key (0,42), partitionable: bits[j] = v0^v1 of tf((0,42),(0,j))
__device__ __forceinline__ unsigned threefry_bits(unsigned j) {
    const unsigned ks0 = 0u, ks1 = 42u, ks2 = 0x1BD11BDAu ^ 42u;
    unsigned x0 = ks0, x1 = j + ks1;
#define RND(r) { x0 += x1; x1 = rotl32(x1, (r)); x1 ^= x0; }
    RND(13) RND(15) RND(26) RND(6)
    x0 += ks1; x1 += ks2 + 1u;
    RND(17) RND(29) RND(16) RND(24)
    x0 += ks2; x1 += ks0 + 2u;
    RND(13) RND(15) RND(26) RND(6)
    x0 += ks0; x1 += ks1 + 3u;
    RND(17) RND(29) RND(16) RND(24)
    x0 += ks1; x1 += ks2 + 4u;
    RND(13) RND(15) RND(26) RND(6)
    x0 += ks2; x1 += ks0 + 5u;
#undef RND
    return x0 ^ x1;
}
__device__ __forceinline__ float gumbel_from_bits(unsigned bits) {
    unsigned m = bits >> 9;
    float u;
    if (m == 0u) u = 1.17549435e-38f;
    else         u = __uint_as_float(0x3F800000u | m) - 1.0f;
    return -logf(-logf(u));
}
__device__ __forceinline__ void decode_edge(int e, int &r, int &c) {
    int t = e + BASE0;
    int rr = (int)((1.0f + sqrtf(8.0f * (float)t + 1.0f)) * 0.5f);
    while (rr * (rr - 1) / 2 > t) --rr;
    while ((rr + 1) * rr / 2 <= t) ++rr;
    r = rr;
    c = t - rr * (rr - 1) / 2;
}
__device__ __forceinline__ float warp_sum(float v) {
    v += __shfl_xor_sync(0xffffffffu, v, 16);
    v += __shfl_xor_sync(0xffffffffu, v, 8);
    v += __shfl_xor_sync(0xffffffffu, v, 4);
    v += __shfl_xor_sync(0xffffffffu, v, 2);
    v += __shfl_xor_sync(0xffffffffu, v, 1);
    return v;
}
// bf16 HMMA m16n8k16, row.col, fp32 accum
__device__ __forceinline__ void mma16816(float4 &d, const uint32_t a[4],
                                         uint32_t b0, uint32_t b1) {
    asm volatile(
        "mma.sync.aligned.m16n8k16.row.col.f32.bf16.bf16.f32 "
        "{%0,%1,%2,%3}, {%4,%5,%6,%7}, {%8,%9}, {%0,%1,%2,%3};"
        : "+f"(d.x), "+f"(d.y), "+f"(d.z), "+f"(d.w)
        : "r"(a[0]), "r"(a[1]), "r"(a[2]), "r"(a[3]), "r"(b0), "r"(b1));
}

// ---------------------------------------------------------------------------
// Kernel 0: zero output + reset approx maxima
// ---------------------------------------------------------------------------
__global__ void init_kernel(float4 *out) {
    int i = blockIdx.x * blockDim.x + threadIdx.x;
    if (i < (BATCH * NN * NN) / 4) out[i] = make_float4(0.f, 0.f, 0.f, 0.f);
    if (blockIdx.x == 0 && threadIdx.x < BATCH * NSAMP) g_bestu[threadIdx.x] = 0u;
}

// ---------------------------------------------------------------------------
// Kernel 1: per-node layer-1 partials (8 nodes per block)
// ---------------------------------------------------------------------------
__global__ void precompute_kernel(const float *__restrict__ nodes,
                                  const float *__restrict__ W1) {
    int f  = threadIdx.x;
    int nb = blockIdx.x * 8;
    __shared__ float sn[8][FEAT];
#pragma unroll
    for (int k = 0; k < 8; ++k) sn[k][f] = nodes[(nb + k) * FEAT + f];
    __syncthreads();
    float a[8], bb[8];
#pragma unroll
    for (int k = 0; k < 8; ++k) { a[k] = 0.f; bb[k] = 0.f; }
    for (int i = 0; i < FEAT; ++i) {
        float wt = W1[i * FEAT + f];
        float wb = W1[(i + FEAT) * FEAT + f];
#pragma unroll
        for (int k = 0; k < 8; ++k) {
            a[k]  += sn[k][i] * wt;
            bb[k] += sn[k][i] * wb;
        }
    }
#pragma unroll
    for (int k = 0; k < 8; ++k) {
        g_A[(nb + k) * FEAT + f]  = a[k];
        g_Bm[(nb + k) * FEAT + f] = bb[k];
    }
}

// ---------------------------------------------------------------------------
// Kernel 2: bf16 HMMA approx pass. 128 edges per block, 4 warps.
// ---------------------------------------------------------------------------
extern __shared__ uint32_t smem_w[];

__global__ void __launch_bounds__(128)
main_mma(const float *__restrict__ b1,  const float *__restrict__ g1,
         const float *__restrict__ be1, const float *__restrict__ W2,
         const float *__restrict__ b2,  const float *__restrict__ g2,
         const float *__restrict__ be2, const float *__restrict__ W3,
         const float *__restrict__ b3) {
    const int tid = threadIdx.x, lane = tid & 31, warp = tid >> 5;
    const int gr = lane >> 2, tg = lane & 3;
    const int b = blockIdx.y;
    const int ebase = blockIdx.x * TILE_M;

    uint32_t *Xw = smem_w;                       // bf16 X tile [128][XS words]
    uint32_t *Ww = smem_w + 128 * XS;            // bf16 W2^T   [128][XS words]
    __shared__ float2   sPar[FEAT];              // (b2[c], g2[c]*W3[c])
    __shared__ float    sSP, sSQ;
    __shared__ unsigned sBest[NSAMP];

    // stage W2^T as bf16: Ww row n holds W2[:, n] over k
    {
        __nv_bfloat16 *W16 = (__nv_bfloat16 *)Ww;
        for (int idx = tid; idx < FEAT * FEAT; idx += 128) {
            int k = idx >> 7, n = idx & 127;
            W16[n * (2 * XS) + k] = __float2bfloat16(W2[idx]);
        }
    }
    // params
    sPar[tid] = make_float2(__ldg(b2 + tid), __ldg(g2 + tid) * __ldg(W3 + tid));
    if (tid < NSAMP) sBest[tid] = 0u;
    if (warp == 0) {
        float p = 0.f, q = 0.f;
#pragma unroll
        for (int c = lane; c < FEAT; c += 32) {
            float w3 = __ldg(W3 + c);
            p += __ldg(g2 + c) * w3;
            q += __ldg(be2 + c) * w3;
        }
        p = warp_sum(p);
        q = warp_sum(q);
        if (lane == 0) { sSP = p; sSQ = q; }
    }

    // Phase A: layer-1 + LN -> bf16 X rows (warp handles 32 edges)
    float c_b1[4], c_g1[4], c_be1[4];
#pragma unroll
    for (int k = 0; k < 4; ++k) {
        int f = lane * 4 + k;
        c_b1[k] = __ldg(b1 + f); c_g1[k] = __ldg(g1 + f); c_be1[k] = __ldg(be1 + f);
    }
    const float *Ab = g_A  + b * NN * FEAT;
    const float *Bb = g_Bm + b * NN * FEAT;
    const int m0 = warp * 32;
#pragma unroll 4
    for (int t = 0; t < 32; ++t) {
        int m = m0 + t;
        int r, c;
        decode_edge(ebase + m, r, c);
        float4 av = *(const float4 *)(Ab + r * FEAT + lane * 4);
        float4 bv = *(const float4 *)(Bb + c * FEAT + lane * 4);
        float h0 = fmaxf(av.x + bv.x + c_b1[0], 0.f);
        float h1 = fmaxf(av.y + bv.y + c_b1[1], 0.f);
        float h2 = fmaxf(av.z + bv.z + c_b1[2], 0.f);
        float h3 = fmaxf(av.w + bv.w + c_b1[3], 0.f);
        float mu = warp_sum(h0 + h1 + h2 + h3) * (1.f / 128.f);
        float d0 = h0 - mu, d1 = h1 - mu, d2 = h2 - mu, d3 = h3 - mu;
        float var = warp_sum(d0 * d0 + d1 * d1 + d2 * d2 + d3 * d3) * (1.f / 128.f);
        float inv = rsqrtf(var + 1e-5f);
        float x0 = d0 * inv * c_g1[0] + c_be1[0];
        float x1 = d1 * inv * c_g1[1] + c_be1[1];
        float x2 = d2 * inv * c_g1[2] + c_be1[2];
        float x3 = d3 * inv * c_g1[3] + c_be1[3];
        __nv_bfloat162 p0 = __floats2bfloat162_rn(x0, x1);
        __nv_bfloat162 p1 = __floats2bfloat162_rn(x2, x3);
        uint2 pk;
        pk.x = *(uint32_t *)&p0;
        pk.y = *(uint32_t *)&p1;
        *(uint2 *)(Xw + m * XS + lane * 2) = pk;
    }
    __syncthreads();

    // MMA: D[128,128] = X @ W2 ; warp owns 2 m16-tiles, 16 n8-tiles, 8 k16-steps
    float4 d[2][16];
#pragma unroll
    for (int mt = 0; mt < 2; ++mt)
#pragma unroll
        for (int nt = 0; nt < 16; ++nt) d[mt][nt] = make_float4(0.f, 0.f, 0.f, 0.f);

    for (int kt = 0; kt < 8; ++kt) {
        const int kw = kt * 8 + tg;
        uint32_t a[2][4];
#pragma unroll
        for (int mt = 0; mt < 2; ++mt) {
            int rowb = m0 + mt * 16 + gr;
            a[mt][0] = Xw[rowb * XS + kw];
            a[mt][1] = Xw[(rowb + 8) * XS + kw];
            a[mt][2] = Xw[rowb * XS + kw + 4];
            a[mt][3] = Xw[(rowb + 8) * XS + kw + 4];
        }
#pragma unroll
        for (int nt = 0; nt < 16; ++nt) {
            uint32_t b0 = Ww[(nt * 8 + gr) * XS + kw];
            uint32_t b1v = Ww[(nt * 8 + gr) * XS + kw + 4];
            mma16816(d[0][nt], a[0], b0, b1v);
            mma16816(d[1][nt], a[1], b0, b1v);
        }
    }

    // Epilogue in fragments: single pass -> S1, S2, SP per row-slot
    const float b3v = __ldg(b3);
    unsigned bestA = 0u, bestB = 0u;
#pragma unroll
    for (int rs = 0; rs < 4; ++rs) {
        const int mt = rs >> 1, hi = rs & 1;
        float S1 = 0.f, S2 = 0.f, SP = 0.f;
#pragma unroll
        for (int nt = 0; nt < 16; ++nt) {
            float4 par = *(const float4 *)&sPar[nt * 8 + tg * 2];
            float v0 = hi ? d[mt][nt].z : d[mt][nt].x;
            float v1 = hi ? d[mt][nt].w : d[mt][nt].y;
            float h0 = fmaxf(v0 + par.x, 0.f);
            float h1 = fmaxf(v1 + par.z, 0.f);
            S1 += h0 + h1;
            S2 += h0 * h0 + h1 * h1;
            SP += h0 * par.y + h1 * par.w;
        }
        S1 += __shfl_xor_sync(0xffffffffu, S1, 1);
        S1 += __shfl_xor_sync(0xffffffffu, S1, 2);
        S2 += __shfl_xor_sync(0xffffffffu, S2, 1);
        S2 += __shfl_xor_sync(0xffffffffu, S2, 2);
        SP += __shfl_xor_sync(0xffffffffu, SP, 1);
        SP += __shfl_xor_sync(0xffffffffu, SP, 2);
        float mu  = S1 * (1.f / 128.f);
        float var = fmaxf(S2 * (1.f / 128.f) - mu * mu, 0.f);
        float inv = rsqrtf(var + 1e-5f);
        float logit = inv * SP - mu * inv * sSP + sSQ + b3v;

        int e = ebase + m0 + mt * 16 + hi * 8 + gr;
        unsigned j = (unsigned)((b * NSAMP + tg) * E_CNT + e);
        float sc = logit + gumbel_from_bits(threefry_bits(j));
        g_scores[j] = sc;
        bestA = max(bestA, flipf(sc));
        if (tg == 0) {
            unsigned j4 = (unsigned)((b * NSAMP + 4) * E_CNT + e);
            float sc4 = logit + gumbel_from_bits(threefry_bits(j4));
            g_scores[j4] = sc4;
            bestB = max(bestB, flipf(sc4));
        }
    }
    bestA = max(bestA, __shfl_xor_sync(0xffffffffu, bestA, 4));
    bestA = max(bestA, __shfl_xor_sync(0xffffffffu, bestA, 8));
    bestA = max(bestA, __shfl_xor_sync(0xffffffffu, bestA, 16));
    bestB = max(bestB, __shfl_xor_sync(0xffffffffu, bestB, 4));
    bestB = max(bestB, __shfl_xor_sync(0xffffffffu, bestB, 8));
    bestB = max(bestB, __shfl_xor_sync(0xffffffffu, bestB, 16));
    if (lane < 4) atomicMax(&sBest[lane], bestA);
    if (lane == 0) atomicMax(&sBest[4], bestB);
    __syncthreads();
    if (tid < NSAMP) atomicMax(&g_bestu[b * NSAMP + tid], sBest[tid]);
}

// ---------------------------------------------------------------------------
// Exact fp32 score for one edge, warp-collective (R2/R3-validated op order)
// ---------------------------------------------------------------------------
__device__ float exact_score(int e, int b, int s,
                             const float *W2, const float *b1, const float *g1,
                             const float *be1, const float *b2, const float *g2,
                             const float *be2, const float *W3, const float *b3,
                             int lane) {
    int r, c;
    decode_edge(e, r, c);
    const float *Ab = g_A  + b * NN * FEAT;
    const float *Bb = g_Bm + b * NN * FEAT;
    float4 av = *(const float4 *)(Ab + r * FEAT + lane * 4);
    float4 bv = *(const float4 *)(Bb + c * FEAT + lane * 4);
    int f = lane * 4;
    float h0 = fmaxf(av.x + bv.x + __ldg(b1 + f + 0), 0.f);
    float h1 = fmaxf(av.y + bv.y + __ldg(b1 + f + 1), 0.f);
    float h2 = fmaxf(av.z + bv.z + __ldg(b1 + f + 2), 0.f);
    float h3 = fmaxf(av.w + bv.w + __ldg(b1 + f + 3), 0.f);
    float mu = warp_sum(h0 + h1 + h2 + h3) * (1.f / 128.f);
    float d0 = h0 - mu, d1 = h1 - mu, d2 = h2 - mu, d3 = h3 - mu;
    float var = warp_sum(d0 * d0 + d1 * d1 + d2 * d2 + d3 * d3) * (1.f / 128.f);
    float inv = rsqrtf(var + 1e-5f);
    float x0 = d0 * inv * __ldg(g1 + f + 0) + __ldg(be1 + f + 0);
    float x1 = d1 * inv * __ldg(g1 + f + 1) + __ldg(be1 + f + 1);
    float x2 = d2 * inv * __ldg(g1 + f + 2) + __ldg(be1 + f + 2);
    float x3 = d3 * inv * __ldg(g1 + f + 3) + __ldg(be1 + f + 3);

    float a0 = 0.f, a1 = 0.f, a2 = 0.f, a3 = 0.f;
    for (int src = 0; src < 32; ++src) {
        float v0 = __shfl_sync(0xffffffffu, x0, src);
        float v1 = __shfl_sync(0xffffffffu, x1, src);
        float v2 = __shfl_sync(0xffffffffu, x2, src);
        float v3 = __shfl_sync(0xffffffffu, x3, src);
        float4 w;
        w = *(const float4 *)(W2 + (src * 4 + 0) * FEAT + f);
        a0 += v0 * w.x; a1 += v0 * w.y; a2 += v0 * w.z; a3 += v0 * w.w;
        w = *(const float4 *)(W2 + (src * 4 + 1) * FEAT + f);
        a0 += v1 * w.x; a1 += v1 * w.y; a2 += v1 * w.z; a3 += v1 * w.w;
        w = *(const float4 *)(W2 + (src * 4 + 2) * FEAT + f);
        a0 += v2 * w.x; a1 += v2 * w.y; a2 += v2 * w.z; a3 += v2 * w.w;
        w = *(const float4 *)(W2 + (src * 4 + 3) * FEAT + f);
        a0 += v3 * w.x; a1 += v3 * w.y; a2 += v3 * w.z; a3 += v3 * w.w;
    }
    h0 = fmaxf(a0 + __ldg(b2 + f + 0), 0.f);
    h1 = fmaxf(a1 + __ldg(b2 + f + 1), 0.f);
    h2 = fmaxf(a2 + __ldg(b2 + f + 2), 0.f);
    h3 = fmaxf(a3 + __ldg(b2 + f + 3), 0.f);
    mu = warp_sum(h0 + h1 + h2 + h3) * (1.f / 128.f);
    d0 = h0 - mu; d1 = h1 - mu; d2 = h2 - mu; d3 = h3 - mu;
    var = warp_sum(d0 * d0 + d1 * d1 + d2 * d2 + d3 * d3) * (1.f / 128.f);
    inv = rsqrtf(var + 1e-5f);
    float y0 = d0 * inv * __ldg(g2 + f + 0) + __ldg(be2 + f + 0);
    float y1 = d1 * inv * __ldg(g2 + f + 1) + __ldg(be2 + f + 1);
    float y2 = d2 * inv * __ldg(g2 + f + 2) + __ldg(be2 + f + 2);
    float y3 = d3 * inv * __ldg(g2 + f + 3) + __ldg(be2 + f + 3);
    float logit = warp_sum(y0 * __ldg(W3 + f + 0) + y1 * __ldg(W3 + f + 1) +
                           y2 * __ldg(W3 + f + 2) + y3 * __ldg(W3 + f + 3)) + __ldg(b3);
    unsigned j = (unsigned)((b * NSAMP + s) * E_CNT + e);
    return logit + gumbel_from_bits(threefry_bits(j));
}

// ---------------------------------------------------------------------------
// Kernel 3: per-(b,s) candidate collection + exact refinement + argmax
// ---------------------------------------------------------------------------
__global__ void __launch_bounds__(256)
refine_kernel(const float *__restrict__ W2, const float *__restrict__ b1,
              const float *__restrict__ g1, const float *__restrict__ be1,
              const float *__restrict__ b2, const float *__restrict__ g2,
              const float *__restrict__ be2, const float *__restrict__ W3,
              const float *__restrict__ b3) {
    const int bs = blockIdx.x;
    const int b = bs / NSAMP, s = bs % NSAMP;
    __shared__ int   s_cnt;
    __shared__ int   s_cand[MAXC];
    __shared__ float s_score[MAXC];
    if (threadIdx.x == 0) s_cnt = 0;
    __syncthreads();

    const float bestA = unflipf(g_bestu[bs]);
    const float thr = bestA - DELTA;
    const float *sc = g_scores + bs * E_CNT;
    for (int e = threadIdx.x; e < E_CNT; e += blockDim.x) {
        if (sc[e] >= thr) {
            int i = atomicAdd(&s_cnt, 1);
            if (i < MAXC) s_cand[i] = e;
        }
    }
    __syncthreads();
    int n = min(s_cnt, MAXC);

    const int warp = threadIdx.x >> 5, lane = threadIdx.x & 31;
    for (int i = warp; i < n; i += 8) {
        float v = exact_score(s_cand[i], b, s, W2, b1, g1, be1, b2, g2, be2, W3, b3, lane);
        if (lane == 0) s_score[i] = v;
    }
    __syncthreads();
    if (threadIdx.x == 0) {
        float best = -__int_as_float(0x7f800000);
        int beste = 0x7FFFFFFF;
        for (int i = 0; i < n; ++i) {
            if (s_score[i] > best || (s_score[i] == best && s_cand[i] < beste)) {
                best = s_score[i];
                beste = s_cand[i];
            }
        }
        g_winner[bs] = beste;
    }
}

// ---------------------------------------------------------------------------
// Kernel 4: scatter winners
// ---------------------------------------------------------------------------
__global__ void finalize_kernel(float *out) {
    int t = threadIdx.x;
    if (t >= BATCH * NSAMP) return;
    int e = g_winner[t];
    int b = t / NSAMP;
    int r, c;
    decode_edge(e, r, c);
    out[b * NN * NN + r * NN + c] = 1.0f;
}

// ---------------------------------------------------------------------------
extern "C" void kernel_launch(void *const *d_in, const int *in_sizes, int n_in,
                              void *d_out, int out_size) {
    const float *nodes = (const float *)d_in[0];
    const float *W1    = (const float *)d_in[1];
    const float *b1    = (const float *)d_in[2];
    const float *g1    = (const float *)d_in[3];
    const float *be1   = (const float *)d_in[4];
    const float *W2    = (const float *)d_in[5];
    const float *b2    = (const float *)d_in[6];
    const float *g2    = (const float *)d_in[7];
    const float *be2   = (const float *)d_in[8];
    const float *W3    = (const float *)d_in[9];
    const float *b3    = (const float *)d_in[10];

    cudaFuncSetAttribute(main_mma, cudaFuncAttributeMaxDynamicSharedMemorySize, SMEM_MAIN);

    init_kernel<<<1024, 256>>>((float4 *)d_out);
    precompute_kernel<<<BATCH * NN / 8, FEAT>>>(nodes, W1);
    main_mma<<<dim3(NTILE, BATCH), 128, SMEM_MAIN>>>(
        b1, g1, be1, W2, b2, g2, be2, W3, b3);
    refine_kernel<<<BATCH * NSAMP, 256>>>(W2, b1, g1, be1, b2, g2, be2, W3, b3);
    finalize_kernel<<<1, 32>>>((float *)d_out);
}

// round 6
// speedup vs baseline: 2.5438x; 1.0045x over previous
#include <cuda_runtime.h>
#include <cuda_bf16.h>
#include <math.h>
#include <stdint.h>

#define FEAT   128
#define NN     512
#define BATCH  4
#define NSAMP  5
#define E_CNT  97920
#define BASE0  32896
#define TILE_M 128
#define NTILE  (E_CNT / TILE_M)     // 765
#define DELTA  0.125f
#define MAXC   128
#define XS     68                   // word stride of bf16 tiles (conflict-free)
#define SMEM_X_BYTES (128 * XS * 4) // 34816
#define SMEM_MAIN (2 * SMEM_X_BYTES)

// ---------------------------------------------------------------------------
// Scratch (static device globals: no allocation allowed)
// ---------------------------------------------------------------------------
__device__ float    g_A[BATCH * NN * FEAT];
__device__ float    g_Bm[BATCH * NN * FEAT];
__device__ float    g_scores[BATCH * NSAMP * E_CNT];   // 7.8 MB
__device__ unsigned g_bestu[BATCH * NSAMP];            // flipped-float approx max
__device__ int      g_winner[BATCH * NSAMP];

// ---------------------------------------------------------------------------
// helpers
// ---------------------------------------------------------------------------
__device__ __forceinline__ unsigned flipf(float f) {
    unsigned u = __float_as_uint(f);
    return (u & 0x80000000u) ? ~u : (u | 0x80000000u);
}
__device__ __forceinline__ float unflipf(unsigned u) {
    return __uint_as_float((u & 0x80000000u) ? (u & 0x7FFFFFFFu) : ~u);
}
__device__ __forceinline__ unsigned rotl32(unsigned v, int s) {
    return (v << s) | (v >> (32 - s));
}
// JAX Threefry-2x32, key (0,42), partitionable: bits[j] = v0^v1 of tf((0,42),(0,j))
__device__ __forceinline__ unsigned threefry_bits(unsigned j) {
    const unsigned ks0 = 0u, ks1 = 42u, ks2 = 0x1BD11BDAu ^ 42u;
    unsigned x0 = ks0, x1 = j + ks1;
#define RND(r) { x0 += x1; x1 = rotl32(x1, (r)); x1 ^= x0; }
    RND(13) RND(15) RND(26) RND(6)
    x0 += ks1; x1 += ks2 + 1u;
    RND(17) RND(29) RND(16) RND(24)
    x0 += ks2; x1 += ks0 + 2u;
    RND(13) RND(15) RND(26) RND(6)
    x0 += ks0; x1 += ks1 + 3u;
    RND(17) RND(29) RND(16) RND(24)
    x0 += ks1; x1 += ks2 + 4u;
    RND(13) RND(15) RND(26) RND(6)
    x0 += ks2; x1 += ks0 + 5u;
#undef RND
    return x0 ^ x1;
}
__device__ __forceinline__ float gumbel_from_bits(unsigned bits) {
    unsigned m = bits >> 9;
    float u;
    if (m == 0u) u = 1.17549435e-38f;
    else         u = __uint_as_float(0x3F800000u | m) - 1.0f;
    return -logf(-logf(u));
}
__device__ __forceinline__ void decode_edge(int e, int &r, int &c) {
    int t = e + BASE0;
    int rr = (int)((1.0f + sqrtf(8.0f * (float)t + 1.0f)) * 0.5f);
    while (rr * (rr - 1) / 2 > t) --rr;
    while ((rr + 1) * rr / 2 <= t) ++rr;
    r = rr;
    c = t - rr * (rr - 1) / 2;
}
__device__ __forceinline__ float warp_sum(float v) {
    v += __shfl_xor_sync(0xffffffffu, v, 16);
    v += __shfl_xor_sync(0xffffffffu, v, 8);
    v += __shfl_xor_sync(0xffffffffu, v, 4);
    v += __shfl_xor_sync(0xffffffffu, v, 2);
    v += __shfl_xor_sync(0xffffffffu, v, 1);
    return v;
}
// bf16 HMMA m16n8k16, row.col, fp32 accum
__device__ __forceinline__ void mma16816(float4 &d, const uint32_t a[4],
                                         uint32_t b0, uint32_t b1) {
    asm volatile(
        "mma.sync.aligned.m16n8k16.row.col.f32.bf16.bf16.f32 "
        "{%0,%1,%2,%3}, {%4,%5,%6,%7}, {%8,%9}, {%0,%1,%2,%3};"
        : "+f"(d.x), "+f"(d.y), "+f"(d.z), "+f"(d.w)
        : "r"(a[0]), "r"(a[1]), "r"(a[2]), "r"(a[3]), "r"(b0), "r"(b1));
}

// ---------------------------------------------------------------------------
// Kernel 0: zero output + reset approx maxima
// ---------------------------------------------------------------------------
__global__ void init_kernel(float4 *out) {
    int i = blockIdx.x * blockDim.x + threadIdx.x;
    if (i < (BATCH * NN * NN) / 4) out[i] = make_float4(0.f, 0.f, 0.f, 0.f);
    if (blockIdx.x == 0 && threadIdx.x < BATCH * NSAMP) g_bestu[threadIdx.x] = 0u;
}

// ---------------------------------------------------------------------------
// Kernel 1: per-node layer-1 partials (8 nodes per block)
// ---------------------------------------------------------------------------
__global__ void precompute_kernel(const float *__restrict__ nodes,
                                  const float *__restrict__ W1) {
    int f  = threadIdx.x;
    int nb = blockIdx.x * 8;
    __shared__ float sn[8][FEAT];
#pragma unroll
    for (int k = 0; k < 8; ++k) sn[k][f] = nodes[(nb + k) * FEAT + f];
    __syncthreads();
    float a[8], bb[8];
#pragma unroll
    for (int k = 0; k < 8; ++k) { a[k] = 0.f; bb[k] = 0.f; }
    for (int i = 0; i < FEAT; ++i) {
        float wt = W1[i * FEAT + f];
        float wb = W1[(i + FEAT) * FEAT + f];
#pragma unroll
        for (int k = 0; k < 8; ++k) {
            a[k]  += sn[k][i] * wt;
            bb[k] += sn[k][i] * wb;
        }
    }
#pragma unroll
    for (int k = 0; k < 8; ++k) {
        g_A[(nb + k) * FEAT + f]  = a[k];
        g_Bm[(nb + k) * FEAT + f] = bb[k];
    }
}

// ---------------------------------------------------------------------------
// Kernel 2: bf16 HMMA approx pass. 128 edges per block, 4 warps.
// ---------------------------------------------------------------------------
extern __shared__ uint32_t smem_w[];

__global__ void __launch_bounds__(128)
main_mma(const float *__restrict__ b1,  const float *__restrict__ g1,
         const float *__restrict__ be1, const float *__restrict__ W2,
         const float *__restrict__ b2,  const float *__restrict__ g2,
         const float *__restrict__ be2, const float *__restrict__ W3,
         const float *__restrict__ b3) {
    const int tid = threadIdx.x, lane = tid & 31, warp = tid >> 5;
    const int gr = lane >> 2, tg = lane & 3;
    const int b = blockIdx.y;
    const int ebase = blockIdx.x * TILE_M;

    uint32_t *Xw = smem_w;                       // bf16 X tile [128][XS words]
    uint32_t *Ww = smem_w + 128 * XS;            // bf16 W2^T   [128][XS words]
    __shared__ float2   sPar[FEAT];              // (b2[c], g2[c]*W3[c])
    __shared__ float    sSP, sSQ;
    __shared__ unsigned sBest[NSAMP];

    // stage W2^T as bf16: Ww row n holds W2[:, n] over k
    {
        __nv_bfloat16 *W16 = (__nv_bfloat16 *)Ww;
        for (int idx = tid; idx < FEAT * FEAT; idx += 128) {
            int k = idx >> 7, n = idx & 127;
            W16[n * (2 * XS) + k] = __float2bfloat16(W2[idx]);
        }
    }
    // params
    sPar[tid] = make_float2(__ldg(b2 + tid), __ldg(g2 + tid) * __ldg(W3 + tid));
    if (tid < NSAMP) sBest[tid] = 0u;
    if (warp == 0) {
        float p = 0.f, q = 0.f;
#pragma unroll
        for (int c = lane; c < FEAT; c += 32) {
            float w3 = __ldg(W3 + c);
            p += __ldg(g2 + c) * w3;
            q += __ldg(be2 + c) * w3;
        }
        p = warp_sum(p);
        q = warp_sum(q);
        if (lane == 0) { sSP = p; sSQ = q; }
    }

    // Phase A: layer-1 + LN -> bf16 X rows (warp handles 32 edges)
    float c_b1[4], c_g1[4], c_be1[4];
#pragma unroll
    for (int k = 0; k < 4; ++k) {
        int f = lane * 4 + k;
        c_b1[k] = __ldg(b1 + f); c_g1[k] = __ldg(g1 + f); c_be1[k] = __ldg(be1 + f);
    }
    const float *Ab = g_A  + b * NN * FEAT;
    const float *Bb = g_Bm + b * NN * FEAT;
    const int m0 = warp * 32;
#pragma unroll 4
    for (int t = 0; t < 32; ++t) {
        int m = m0 + t;
        int r, c;
        decode_edge(ebase + m, r, c);
        float4 av = *(const float4 *)(Ab + r * FEAT + lane * 4);
        float4 bv = *(const float4 *)(Bb + c * FEAT + lane * 4);
        float h0 = fmaxf(av.x + bv.x + c_b1[0], 0.f);
        float h1 = fmaxf(av.y + bv.y + c_b1[1], 0.f);
        float h2 = fmaxf(av.z + bv.z + c_b1[2], 0.f);
        float h3 = fmaxf(av.w + bv.w + c_b1[3], 0.f);
        float mu = warp_sum(h0 + h1 + h2 + h3) * (1.f / 128.f);
        float d0 = h0 - mu, d1 = h1 - mu, d2 = h2 - mu, d3 = h3 - mu;
        float var = warp_sum(d0 * d0 + d1 * d1 + d2 * d2 + d3 * d3) * (1.f / 128.f);
        float inv = rsqrtf(var + 1e-5f);
        float x0 = d0 * inv * c_g1[0] + c_be1[0];
        float x1 = d1 * inv * c_g1[1] + c_be1[1];
        float x2 = d2 * inv * c_g1[2] + c_be1[2];
        float x3 = d3 * inv * c_g1[3] + c_be1[3];
        __nv_bfloat162 p0 = __floats2bfloat162_rn(x0, x1);
        __nv_bfloat162 p1 = __floats2bfloat162_rn(x2, x3);
        uint2 pk;
        pk.x = *(uint32_t *)&p0;
        pk.y = *(uint32_t *)&p1;
        *(uint2 *)(Xw + m * XS + lane * 2) = pk;
    }
    __syncthreads();

    // MMA: D[128,128] = X @ W2 ; warp owns 2 m16-tiles, 16 n8-tiles, 8 k16-steps
    float4 d[2][16];
#pragma unroll
    for (int mt = 0; mt < 2; ++mt)
#pragma unroll
        for (int nt = 0; nt < 16; ++nt) d[mt][nt] = make_float4(0.f, 0.f, 0.f, 0.f);

    for (int kt = 0; kt < 8; ++kt) {
        const int kw = kt * 8 + tg;
        uint32_t a[2][4];
#pragma unroll
        for (int mt = 0; mt < 2; ++mt) {
            int rowb = m0 + mt * 16 + gr;
            a[mt][0] = Xw[rowb * XS + kw];
            a[mt][1] = Xw[(rowb + 8) * XS + kw];
            a[mt][2] = Xw[rowb * XS + kw + 4];
            a[mt][3] = Xw[(rowb + 8) * XS + kw + 4];
        }
#pragma unroll
        for (int nt = 0; nt < 16; ++nt) {
            uint32_t b0 = Ww[(nt * 8 + gr) * XS + kw];
            uint32_t b1v = Ww[(nt * 8 + gr) * XS + kw + 4];
            mma16816(d[0][nt], a[0], b0, b1v);
            mma16816(d[1][nt], a[1], b0, b1v);
        }
    }

    // Epilogue in fragments: single pass -> S1, S2, SP per row-slot
    const float b3v = __ldg(b3);
    unsigned bestA = 0u, bestB = 0u;
#pragma unroll
    for (int rs = 0; rs < 4; ++rs) {
        const int mt = rs >> 1, hi = rs & 1;
        float S1 = 0.f, S2 = 0.f, SP = 0.f;
#pragma unroll
        for (int nt = 0; nt < 16; ++nt) {
            float4 par = *(const float4 *)&sPar[nt * 8 + tg * 2];
            float v0 = hi ? d[mt][nt].z : d[mt][nt].x;
            float v1 = hi ? d[mt][nt].w : d[mt][nt].y;
            float h0 = fmaxf(v0 + par.x, 0.f);
            float h1 = fmaxf(v1 + par.z, 0.f);
            S1 += h0 + h1;
            S2 += h0 * h0 + h1 * h1;
            SP += h0 * par.y + h1 * par.w;
        }
        S1 += __shfl_xor_sync(0xffffffffu, S1, 1);
        S1 += __shfl_xor_sync(0xffffffffu, S1, 2);
        S2 += __shfl_xor_sync(0xffffffffu, S2, 1);
        S2 += __shfl_xor_sync(0xffffffffu, S2, 2);
        SP += __shfl_xor_sync(0xffffffffu, SP, 1);
        SP += __shfl_xor_sync(0xffffffffu, SP, 2);
        float mu  = S1 * (1.f / 128.f);
        float var = fmaxf(S2 * (1.f / 128.f) - mu * mu, 0.f);
        float inv = rsqrtf(var + 1e-5f);
        float logit = inv * SP - mu * inv * sSP + sSQ + b3v;

        int e = ebase + m0 + mt * 16 + hi * 8 + gr;
        unsigned j = (unsigned)((b * NSAMP + tg) * E_CNT + e);
        float sc = logit + gumbel_from_bits(threefry_bits(j));
        g_scores[j] = sc;
        bestA = max(bestA, flipf(sc));
        if (tg == 0) {
            unsigned j4 = (unsigned)((b * NSAMP + 4) * E_CNT + e);
            float sc4 = logit + gumbel_from_bits(threefry_bits(j4));
            g_scores[j4] = sc4;
            bestB = max(bestB, flipf(sc4));
        }
    }
    bestA = max(bestA, __shfl_xor_sync(0xffffffffu, bestA, 4));
    bestA = max(bestA, __shfl_xor_sync(0xffffffffu, bestA, 8));
    bestA = max(bestA, __shfl_xor_sync(0xffffffffu, bestA, 16));
    bestB = max(bestB, __shfl_xor_sync(0xffffffffu, bestB, 4));
    bestB = max(bestB, __shfl_xor_sync(0xffffffffu, bestB, 8));
    bestB = max(bestB, __shfl_xor_sync(0xffffffffu, bestB, 16));
    if (lane < 4) atomicMax(&sBest[lane], bestA);
    if (lane == 0) atomicMax(&sBest[4], bestB);
    __syncthreads();
    if (tid < NSAMP) atomicMax(&g_bestu[b * NSAMP + tid], sBest[tid]);
}

// ---------------------------------------------------------------------------
// Exact fp32 score for one edge, warp-collective (R2/R3-validated op order)
// ---------------------------------------------------------------------------
__device__ float exact_score(int e, int b, int s,
                             const float *W2, const float *b1, const float *g1,
                             const float *be1, const float *b2, const float *g2,
                             const float *be2, const float *W3, const float *b3,
                             int lane) {
    int r, c;
    decode_edge(e, r, c);
    const float *Ab = g_A  + b * NN * FEAT;
    const float *Bb = g_Bm + b * NN * FEAT;
    float4 av = *(const float4 *)(Ab + r * FEAT + lane * 4);
    float4 bv = *(const float4 *)(Bb + c * FEAT + lane * 4);
    int f = lane * 4;
    float h0 = fmaxf(av.x + bv.x + __ldg(b1 + f + 0), 0.f);
    float h1 = fmaxf(av.y + bv.y + __ldg(b1 + f + 1), 0.f);
    float h2 = fmaxf(av.z + bv.z + __ldg(b1 + f + 2), 0.f);
    float h3 = fmaxf(av.w + bv.w + __ldg(b1 + f + 3), 0.f);
    float mu = warp_sum(h0 + h1 + h2 + h3) * (1.f / 128.f);
    float d0 = h0 - mu, d1 = h1 - mu, d2 = h2 - mu, d3 = h3 - mu;
    float var = warp_sum(d0 * d0 + d1 * d1 + d2 * d2 + d3 * d3) * (1.f / 128.f);
    float inv = rsqrtf(var + 1e-5f);
    float x0 = d0 * inv * __ldg(g1 + f + 0) + __ldg(be1 + f + 0);
    float x1 = d1 * inv * __ldg(g1 + f + 1) + __ldg(be1 + f + 1);
    float x2 = d2 * inv * __ldg(g1 + f + 2) + __ldg(be1 + f + 2);
    float x3 = d3 * inv * __ldg(g1 + f + 3) + __ldg(be1 + f + 3);

    float a0 = 0.f, a1 = 0.f, a2 = 0.f, a3 = 0.f;
    for (int src = 0; src < 32; ++src) {
        float v0 = __shfl_sync(0xffffffffu, x0, src);
        float v1 = __shfl_sync(0xffffffffu, x1, src);
        float v2 = __shfl_sync(0xffffffffu, x2, src);
        float v3 = __shfl_sync(0xffffffffu, x3, src);
        float4 w;
        w = *(const float4 *)(W2 + (src * 4 + 0) * FEAT + f);
        a0 += v0 * w.x; a1 += v0 * w.y; a2 += v0 * w.z; a3 += v0 * w.w;
        w = *(const float4 *)(W2 + (src * 4 + 1) * FEAT + f);
        a0 += v1 * w.x; a1 += v1 * w.y; a2 += v1 * w.z; a3 += v1 * w.w;
        w = *(const float4 *)(W2 + (src * 4 + 2) * FEAT + f);
        a0 += v2 * w.x; a1 += v2 * w.y; a2 += v2 * w.z; a3 += v2 * w.w;
        w = *(const float4 *)(W2 + (src * 4 + 3) * FEAT + f);
        a0 += v3 * w.x; a1 += v3 * w.y; a2 += v3 * w.z; a3 += v3 * w.w;
    }
    h0 = fmaxf(a0 + __ldg(b2 + f + 0), 0.f);
    h1 = fmaxf(a1 + __ldg(b2 + f + 1), 0.f);
    h2 = fmaxf(a2 + __ldg(b2 + f + 2), 0.f);
    h3 = fmaxf(a3 + __ldg(b2 + f + 3), 0.f);
    mu = warp_sum(h0 + h1 + h2 + h3) * (1.f / 128.f);
    d0 = h0 - mu; d1 = h1 - mu; d2 = h2 - mu; d3 = h3 - mu;
    var = warp_sum(d0 * d0 + d1 * d1 + d2 * d2 + d3 * d3) * (1.f / 128.f);
    inv = rsqrtf(var + 1e-5f);
    float y0 = d0 * inv * __ldg(g2 + f + 0) + __ldg(be2 + f + 0);
    float y1 = d1 * inv * __ldg(g2 + f + 1) + __ldg(be2 + f + 1);
    float y2 = d2 * inv * __ldg(g2 + f + 2) + __ldg(be2 + f + 2);
    float y3 = d3 * inv * __ldg(g2 + f + 3) + __ldg(be2 + f + 3);
    float logit = warp_sum(y0 * __ldg(W3 + f + 0) + y1 * __ldg(W3 + f + 1) +
                           y2 * __ldg(W3 + f + 2) + y3 * __ldg(W3 + f + 3)) + __ldg(b3);
    unsigned j = (unsigned)((b * NSAMP + s) * E_CNT + e);
    return logit + gumbel_from_bits(threefry_bits(j));
}

// ---------------------------------------------------------------------------
// Kernel 3: per-(b,s) candidate collection + exact refinement + argmax
// ---------------------------------------------------------------------------
__global__ void __launch_bounds__(256)
refine_kernel(const float *__restrict__ W2, const float *__restrict__ b1,
              const float *__restrict__ g1, const float *__restrict__ be1,
              const float *__restrict__ b2, const float *__restrict__ g2,
              const float *__restrict__ be2, const float *__restrict__ W3,
              const float *__restrict__ b3) {
    const int bs = blockIdx.x;
    const int b = bs / NSAMP, s = bs % NSAMP;
    __shared__ int   s_cnt;
    __shared__ int   s_cand[MAXC];
    __shared__ float s_score[MAXC];
    if (threadIdx.x == 0) s_cnt = 0;
    __syncthreads();

    const float bestA = unflipf(g_bestu[bs]);
    const float thr = bestA - DELTA;
    const float *sc = g_scores + bs * E_CNT;
    for (int e = threadIdx.x; e < E_CNT; e += blockDim.x) {
        if (sc[e] >= thr) {
            int i = atomicAdd(&s_cnt, 1);
            if (i < MAXC) s_cand[i] = e;
        }
    }
    __syncthreads();
    int n = min(s_cnt, MAXC);

    const int warp = threadIdx.x >> 5, lane = threadIdx.x & 31;
    for (int i = warp; i < n; i += 8) {
        float v = exact_score(s_cand[i], b, s, W2, b1, g1, be1, b2, g2, be2, W3, b3, lane);
        if (lane == 0) s_score[i] = v;
    }
    __syncthreads();
    if (threadIdx.x == 0) {
        float best = -__int_as_float(0x7f800000);
        int beste = 0x7FFFFFFF;
        for (int i = 0; i < n; ++i) {
            if (s_score[i] > best || (s_score[i] == best && s_cand[i] < beste)) {
                best = s_score[i];
                beste = s_cand[i];
            }
        }
        g_winner[bs] = beste;
    }
}

// ---------------------------------------------------------------------------
// Kernel 4: scatter winners
// ---------------------------------------------------------------------------
__global__ void finalize_kernel(float *out) {
    int t = threadIdx.x;
    if (t >= BATCH * NSAMP) return;
    int e = g_winner[t];
    int b = t / NSAMP;
    int r, c;
    decode_edge(e, r, c);
    out[b * NN * NN + r * NN + c] = 1.0f;
}

// ---------------------------------------------------------------------------
extern "C" void kernel_launch(void *const *d_in, const int *in_sizes, int n_in,
                              void *d_out, int out_size) {
    const float *nodes = (const float *)d_in[0];
    const float *W1    = (const float *)d_in[1];
    const float *b1    = (const float *)d_in[2];
    const float *g1    = (const float *)d_in[3];
    const float *be1   = (const float *)d_in[4];
    const float *W2    = (const float *)d_in[5];
    const float *b2    = (const float *)d_in[6];
    const float *g2    = (const float *)d_in[7];
    const float *be2   = (const float *)d_in[8];
    const float *W3    = (const float *)d_in[9];
    const float *b3    = (const float *)d_in[10];

    cudaFuncSetAttribute(main_mma, cudaFuncAttributeMaxDynamicSharedMemorySize, SMEM_MAIN);

    init_kernel<<<1024, 256>>>((float4 *)d_out);
    precompute_kernel<<<BATCH * NN / 8, FEAT>>>(nodes, W1);
    main_mma<<<dim3(NTILE, BATCH), 128, SMEM_MAIN>>>(
        b1, g1, be1, W2, b2, g2, be2, W3, b3);
    refine_kernel<<<BATCH * NSAMP, 256>>>(W2, b1, g1, be1, b2, g2, be2, W3, b3);
    finalize_kernel<<<1, 32>>>((float *)d_out);
}

// round 7
// speedup vs baseline: 2.5457x; 1.0007x over previous
#include <cuda_runtime.h>
#include <cuda_bf16.h>
#include <math.h>
#include <stdint.h>

#define FEAT   128
#define NN     512
#define BATCH  4
#define NSAMP  5
#define E_CNT  97920
#define BASE0  32896
#define TILE_M 128
#define NTILE  (E_CNT / TILE_M)     // 765
#define DELTA  0.125f
#define MAXC   128
#define XS     68                   // word stride of bf16 tiles (conflict-free)
#define SMEM_X_BYTES (128 * XS * 4) // 34816
#define SMEM_MAIN (2 * SMEM_X_BYTES)

// ---------------------------------------------------------------------------
// Scratch (static device globals: no allocation allowed)
// ---------------------------------------------------------------------------
__device__ float    g_A[BATCH * NN * FEAT];
__device__ float    g_Bm[BATCH * NN * FEAT];
__device__ float    g_scores[BATCH * NSAMP * E_CNT];   // 7.8 MB
__device__ unsigned g_bestu[BATCH * NSAMP];            // flipped-float approx max
__device__ int      g_winner[BATCH * NSAMP];

// ---------------------------------------------------------------------------
// helpers
// ---------------------------------------------------------------------------
__device__ __forceinline__ unsigned flipf(float f) {
    unsigned u = __float_as_uint(f);
    return (u & 0x80000000u) ? ~u : (u | 0x80000000u);
}
__device__ __forceinline__ float unflipf(unsigned u) {
    return __uint_as_float((u & 0x80000000u) ? (u & 0x7FFFFFFFu) : ~u);
}
__device__ __forceinline__ unsigned rotl32(unsigned v, int s) {
    return (v << s) | (v >> (32 - s));
}
// JAX Threefry-2x32, key (0,42), partitionable: bits[j] = v0^v1 of tf((0,42),(0,j))
__device__ __forceinline__ unsigned threefry_bits(unsigned j) {
    const unsigned ks0 = 0u, ks1 = 42u, ks2 = 0x1BD11BDAu ^ 42u;
    unsigned x0 = ks0, x1 = j + ks1;
#define RND(r) { x0 += x1; x1 = rotl32(x1, (r)); x1 ^= x0; }
    RND(13) RND(15) RND(26) RND(6)
    x0 += ks1; x1 += ks2 + 1u;
    RND(17) RND(29) RND(16) RND(24)
    x0 += ks2; x1 += ks0 + 2u;
    RND(13) RND(15) RND(26) RND(6)
    x0 += ks0; x1 += ks1 + 3u;
    RND(17) RND(29) RND(16) RND(24)
    x0 += ks1; x1 += ks2 + 4u;
    RND(13) RND(15) RND(26) RND(6)
    x0 += ks2; x1 += ks0 + 5u;
#undef RND
    return x0 ^ x1;
}
__device__ __forceinline__ float gumbel_from_bits(unsigned bits) {
    unsigned m = bits >> 9;
    float u;
    if (m == 0u) u = 1.17549435e-38f;
    else         u = __uint_as_float(0x3F800000u | m) - 1.0f;
    return -logf(-logf(u));
}
__device__ __forceinline__ void decode_edge(int e, int &r, int &c) {
    int t = e + BASE0;
    int rr = (int)((1.0f + sqrtf(8.0f * (float)t + 1.0f)) * 0.5f);
    while (rr * (rr - 1) / 2 > t) --rr;
    while ((rr + 1) * rr / 2 <= t) ++rr;
    r = rr;
    c = t - rr * (rr - 1) / 2;
}
__device__ __forceinline__ float warp_sum(float v) {
    v += __shfl_xor_sync(0xffffffffu, v, 16);
    v += __shfl_xor_sync(0xffffffffu, v, 8);
    v += __shfl_xor_sync(0xffffffffu, v, 4);
    v += __shfl_xor_sync(0xffffffffu, v, 2);
    v += __shfl_xor_sync(0xffffffffu, v, 1);
    return v;
}
// bf16 HMMA m16n8k16, row.col, fp32 accum
__device__ __forceinline__ void mma16816(float4 &d, const uint32_t a[4],
                                         uint32_t b0, uint32_t b1) {
    asm volatile(
        "mma.sync.aligned.m16n8k16.row.col.f32.bf16.bf16.f32 "
        "{%0,%1,%2,%3}, {%4,%5,%6,%7}, {%8,%9}, {%0,%1,%2,%3};"
        : "+f"(d.x), "+f"(d.y), "+f"(d.z), "+f"(d.w)
        : "r"(a[0]), "r"(a[1]), "r"(a[2]), "r"(a[3]), "r"(b0), "r"(b1));
}

// ---------------------------------------------------------------------------
// Kernel 0: zero output + reset approx maxima
// ---------------------------------------------------------------------------
__global__ void init_kernel(float4 *out) {
    int i = blockIdx.x * blockDim.x + threadIdx.x;
    if (i < (BATCH * NN * NN) / 4) out[i] = make_float4(0.f, 0.f, 0.f, 0.f);
    if (blockIdx.x == 0 && threadIdx.x < BATCH * NSAMP) g_bestu[threadIdx.x] = 0u;
}

// ---------------------------------------------------------------------------
// Kernel 1: per-node layer-1 partials (8 nodes per block)
// ---------------------------------------------------------------------------
__global__ void precompute_kernel(const float *__restrict__ nodes,
                                  const float *__restrict__ W1) {
    int f  = threadIdx.x;
    int nb = blockIdx.x * 8;
    __shared__ float sn[8][FEAT];
#pragma unroll
    for (int k = 0; k < 8; ++k) sn[k][f] = nodes[(nb + k) * FEAT + f];
    __syncthreads();
    float a[8], bb[8];
#pragma unroll
    for (int k = 0; k < 8; ++k) { a[k] = 0.f; bb[k] = 0.f; }
    for (int i = 0; i < FEAT; ++i) {
        float wt = W1[i * FEAT + f];
        float wb = W1[(i + FEAT) * FEAT + f];
#pragma unroll
        for (int k = 0; k < 8; ++k) {
            a[k]  += sn[k][i] * wt;
            bb[k] += sn[k][i] * wb;
        }
    }
#pragma unroll
    for (int k = 0; k < 8; ++k) {
        g_A[(nb + k) * FEAT + f]  = a[k];
        g_Bm[(nb + k) * FEAT + f] = bb[k];
    }
}

// ---------------------------------------------------------------------------
// Kernel 2: bf16 HMMA approx pass. 128 edges per block, 4 warps.
// ---------------------------------------------------------------------------
extern __shared__ uint32_t smem_w[];

__global__ void __launch_bounds__(128)
main_mma(const float *__restrict__ b1,  const float *__restrict__ g1,
         const float *__restrict__ be1, const float *__restrict__ W2,
         const float *__restrict__ b2,  const float *__restrict__ g2,
         const float *__restrict__ be2, const float *__restrict__ W3,
         const float *__restrict__ b3) {
    const int tid = threadIdx.x, lane = tid & 31, warp = tid >> 5;
    const int gr = lane >> 2, tg = lane & 3;
    const int b = blockIdx.y;
    const int ebase = blockIdx.x * TILE_M;

    uint32_t *Xw = smem_w;                       // bf16 X tile [128][XS words]
    uint32_t *Ww = smem_w + 128 * XS;            // bf16 W2^T   [128][XS words]
    __shared__ float2   sPar[FEAT];              // (b2[c], g2[c]*W3[c])
    __shared__ float    sSP, sSQ;
    __shared__ unsigned sBest[NSAMP];

    // stage W2^T as bf16: Ww row n holds W2[:, n] over k
    {
        __nv_bfloat16 *W16 = (__nv_bfloat16 *)Ww;
        for (int idx = tid; idx < FEAT * FEAT; idx += 128) {
            int k = idx >> 7, n = idx & 127;
            W16[n * (2 * XS) + k] = __float2bfloat16(W2[idx]);
        }
    }
    // params
    sPar[tid] = make_float2(__ldg(b2 + tid), __ldg(g2 + tid) * __ldg(W3 + tid));
    if (tid < NSAMP) sBest[tid] = 0u;
    if (warp == 0) {
        float p = 0.f, q = 0.f;
#pragma unroll
        for (int c = lane; c < FEAT; c += 32) {
            float w3 = __ldg(W3 + c);
            p += __ldg(g2 + c) * w3;
            q += __ldg(be2 + c) * w3;
        }
        p = warp_sum(p);
        q = warp_sum(q);
        if (lane == 0) { sSP = p; sSQ = q; }
    }

    // Phase A: layer-1 + LN -> bf16 X rows (warp handles 32 edges)
    float c_b1[4], c_g1[4], c_be1[4];
#pragma unroll
    for (int k = 0; k < 4; ++k) {
        int f = lane * 4 + k;
        c_b1[k] = __ldg(b1 + f); c_g1[k] = __ldg(g1 + f); c_be1[k] = __ldg(be1 + f);
    }
    const float *Ab = g_A  + b * NN * FEAT;
    const float *Bb = g_Bm + b * NN * FEAT;
    const int m0 = warp * 32;
#pragma unroll 4
    for (int t = 0; t < 32; ++t) {
        int m = m0 + t;
        int r, c;
        decode_edge(ebase + m, r, c);
        float4 av = *(const float4 *)(Ab + r * FEAT + lane * 4);
        float4 bv = *(const float4 *)(Bb + c * FEAT + lane * 4);
        float h0 = fmaxf(av.x + bv.x + c_b1[0], 0.f);
        float h1 = fmaxf(av.y + bv.y + c_b1[1], 0.f);
        float h2 = fmaxf(av.z + bv.z + c_b1[2], 0.f);
        float h3 = fmaxf(av.w + bv.w + c_b1[3], 0.f);
        float mu = warp_sum(h0 + h1 + h2 + h3) * (1.f / 128.f);
        float d0 = h0 - mu, d1 = h1 - mu, d2 = h2 - mu, d3 = h3 - mu;
        float var = warp_sum(d0 * d0 + d1 * d1 + d2 * d2 + d3 * d3) * (1.f / 128.f);
        float inv = rsqrtf(var + 1e-5f);
        float x0 = d0 * inv * c_g1[0] + c_be1[0];
        float x1 = d1 * inv * c_g1[1] + c_be1[1];
        float x2 = d2 * inv * c_g1[2] + c_be1[2];
        float x3 = d3 * inv * c_g1[3] + c_be1[3];
        __nv_bfloat162 p0 = __floats2bfloat162_rn(x0, x1);
        __nv_bfloat162 p1 = __floats2bfloat162_rn(x2, x3);
        uint2 pk;
        pk.x = *(uint32_t *)&p0;
        pk.y = *(uint32_t *)&p1;
        *(uint2 *)(Xw + m * XS + lane * 2) = pk;
    }
    __syncthreads();

    // MMA: D[128,128] = X @ W2 ; warp owns 2 m16-tiles, 16 n8-tiles, 8 k16-steps
    float4 d[2][16];
#pragma unroll
    for (int mt = 0; mt < 2; ++mt)
#pragma unroll
        for (int nt = 0; nt < 16; ++nt) d[mt][nt] = make_float4(0.f, 0.f, 0.f, 0.f);

    for (int kt = 0; kt < 8; ++kt) {
        const int kw = kt * 8 + tg;
        uint32_t a[2][4];
#pragma unroll
        for (int mt = 0; mt < 2; ++mt) {
            int rowb = m0 + mt * 16 + gr;
            a[mt][0] = Xw[rowb * XS + kw];
            a[mt][1] = Xw[(rowb + 8) * XS + kw];
            a[mt][2] = Xw[rowb * XS + kw + 4];
            a[mt][3] = Xw[(rowb + 8) * XS + kw + 4];
        }
#pragma unroll
        for (int nt = 0; nt < 16; ++nt) {
            uint32_t b0 = Ww[(nt * 8 + gr) * XS + kw];
            uint32_t b1v = Ww[(nt * 8 + gr) * XS + kw + 4];
            mma16816(d[0][nt], a[0], b0, b1v);
            mma16816(d[1][nt], a[1], b0, b1v);
        }
    }

    // Epilogue in fragments: single pass -> S1, S2, SP per row-slot
    const float b3v = __ldg(b3);
    unsigned bestA = 0u, bestB = 0u;
#pragma unroll
    for (int rs = 0; rs < 4; ++rs) {
        const int mt = rs >> 1, hi = rs & 1;
        float S1 = 0.f, S2 = 0.f, SP = 0.f;
#pragma unroll
        for (int nt = 0; nt < 16; ++nt) {
            float4 par = *(const float4 *)&sPar[nt * 8 + tg * 2];
            float v0 = hi ? d[mt][nt].z : d[mt][nt].x;
            float v1 = hi ? d[mt][nt].w : d[mt][nt].y;
            float h0 = fmaxf(v0 + par.x, 0.f);
            float h1 = fmaxf(v1 + par.z, 0.f);
            S1 += h0 + h1;
            S2 += h0 * h0 + h1 * h1;
            SP += h0 * par.y + h1 * par.w;
        }
        S1 += __shfl_xor_sync(0xffffffffu, S1, 1);
        S1 += __shfl_xor_sync(0xffffffffu, S1, 2);
        S2 += __shfl_xor_sync(0xffffffffu, S2, 1);
        S2 += __shfl_xor_sync(0xffffffffu, S2, 2);
        SP += __shfl_xor_sync(0xffffffffu, SP, 1);
        SP += __shfl_xor_sync(0xffffffffu, SP, 2);
        float mu  = S1 * (1.f / 128.f);
        float var = fmaxf(S2 * (1.f / 128.f) - mu * mu, 0.f);
        float inv = rsqrtf(var + 1e-5f);
        float logit = inv * SP - mu * inv * sSP + sSQ + b3v;

        int e = ebase + m0 + mt * 16 + hi * 8 + gr;
        unsigned j = (unsigned)((b * NSAMP + tg) * E_CNT + e);
        float sc = logit + gumbel_from_bits(threefry_bits(j));
        g_scores[j] = sc;
        bestA = max(bestA, flipf(sc));
        if (tg == 0) {
            unsigned j4 = (unsigned)((b * NSAMP + 4) * E_CNT + e);
            float sc4 = logit + gumbel_from_bits(threefry_bits(j4));
            g_scores[j4] = sc4;
            bestB = max(bestB, flipf(sc4));
        }
    }
    bestA = max(bestA, __shfl_xor_sync(0xffffffffu, bestA, 4));
    bestA = max(bestA, __shfl_xor_sync(0xffffffffu, bestA, 8));
    bestA = max(bestA, __shfl_xor_sync(0xffffffffu, bestA, 16));
    bestB = max(bestB, __shfl_xor_sync(0xffffffffu, bestB, 4));
    bestB = max(bestB, __shfl_xor_sync(0xffffffffu, bestB, 8));
    bestB = max(bestB, __shfl_xor_sync(0xffffffffu, bestB, 16));
    if (lane < 4) atomicMax(&sBest[lane], bestA);
    if (lane == 0) atomicMax(&sBest[4], bestB);
    __syncthreads();
    if (tid < NSAMP) atomicMax(&g_bestu[b * NSAMP + tid], sBest[tid]);
}

// ---------------------------------------------------------------------------
// Exact fp32 score for one edge, warp-collective (R2/R3-validated op order)
// ---------------------------------------------------------------------------
__device__ float exact_score(int e, int b, int s,
                             const float *W2, const float *b1, const float *g1,
                             const float *be1, const float *b2, const float *g2,
                             const float *be2, const float *W3, const float *b3,
                             int lane) {
    int r, c;
    decode_edge(e, r, c);
    const float *Ab = g_A  + b * NN * FEAT;
    const float *Bb = g_Bm + b * NN * FEAT;
    float4 av = *(const float4 *)(Ab + r * FEAT + lane * 4);
    float4 bv = *(const float4 *)(Bb + c * FEAT + lane * 4);
    int f = lane * 4;
    float h0 = fmaxf(av.x + bv.x + __ldg(b1 + f + 0), 0.f);
    float h1 = fmaxf(av.y + bv.y + __ldg(b1 + f + 1), 0.f);
    float h2 = fmaxf(av.z + bv.z + __ldg(b1 + f + 2), 0.f);
    float h3 = fmaxf(av.w + bv.w + __ldg(b1 + f + 3), 0.f);
    float mu = warp_sum(h0 + h1 + h2 + h3) * (1.f / 128.f);
    float d0 = h0 - mu, d1 = h1 - mu, d2 = h2 - mu, d3 = h3 - mu;
    float var = warp_sum(d0 * d0 + d1 * d1 + d2 * d2 + d3 * d3) * (1.f / 128.f);
    float inv = rsqrtf(var + 1e-5f);
    float x0 = d0 * inv * __ldg(g1 + f + 0) + __ldg(be1 + f + 0);
    float x1 = d1 * inv * __ldg(g1 + f + 1) + __ldg(be1 + f + 1);
    float x2 = d2 * inv * __ldg(g1 + f + 2) + __ldg(be1 + f + 2);
    float x3 = d3 * inv * __ldg(g1 + f + 3) + __ldg(be1 + f + 3);

    float a0 = 0.f, a1 = 0.f, a2 = 0.f, a3 = 0.f;
    for (int src = 0; src < 32; ++src) {
        float v0 = __shfl_sync(0xffffffffu, x0, src);
        float v1 = __shfl_sync(0xffffffffu, x1, src);
        float v2 = __shfl_sync(0xffffffffu, x2, src);
        float v3 = __shfl_sync(0xffffffffu, x3, src);
        float4 w;
        w = *(const float4 *)(W2 + (src * 4 + 0) * FEAT + f);
        a0 += v0 * w.x; a1 += v0 * w.y; a2 += v0 * w.z; a3 += v0 * w.w;
        w = *(const float4 *)(W2 + (src * 4 + 1) * FEAT + f);
        a0 += v1 * w.x; a1 += v1 * w.y; a2 += v1 * w.z; a3 += v1 * w.w;
        w = *(const float4 *)(W2 + (src * 4 + 2) * FEAT + f);
        a0 += v2 * w.x; a1 += v2 * w.y; a2 += v2 * w.z; a3 += v2 * w.w;
        w = *(const float4 *)(W2 + (src * 4 + 3) * FEAT + f);
        a0 += v3 * w.x; a1 += v3 * w.y; a2 += v3 * w.z; a3 += v3 * w.w;
    }
    h0 = fmaxf(a0 + __ldg(b2 + f + 0), 0.f);
    h1 = fmaxf(a1 + __ldg(b2 + f + 1), 0.f);
    h2 = fmaxf(a2 + __ldg(b2 + f + 2), 0.f);
    h3 = fmaxf(a3 + __ldg(b2 + f + 3), 0.f);
    mu = warp_sum(h0 + h1 + h2 + h3) * (1.f / 128.f);
    d0 = h0 - mu; d1 = h1 - mu; d2 = h2 - mu; d3 = h3 - mu;
    var = warp_sum(d0 * d0 + d1 * d1 + d2 * d2 + d3 * d3) * (1.f / 128.f);
    inv = rsqrtf(var + 1e-5f);
    float y0 = d0 * inv * __ldg(g2 + f + 0) + __ldg(be2 + f + 0);
    float y1 = d1 * inv * __ldg(g2 + f + 1) + __ldg(be2 + f + 1);
    float y2 = d2 * inv * __ldg(g2 + f + 2) + __ldg(be2 + f + 2);
    float y3 = d3 * inv * __ldg(g2 + f + 3) + __ldg(be2 + f + 3);
    float logit = warp_sum(y0 * __ldg(W3 + f + 0) + y1 * __ldg(W3 + f + 1) +
                           y2 * __ldg(W3 + f + 2) + y3 * __ldg(W3 + f + 3)) + __ldg(b3);
    unsigned j = (unsigned)((b * NSAMP + s) * E_CNT + e);
    return logit + gumbel_from_bits(threefry_bits(j));
}

// ---------------------------------------------------------------------------
// Kernel 3: per-(b,s) candidate collection + exact refinement + argmax
// ---------------------------------------------------------------------------
__global__ void __launch_bounds__(256)
refine_kernel(const float *__restrict__ W2, const float *__restrict__ b1,
              const float *__restrict__ g1, const float *__restrict__ be1,
              const float *__restrict__ b2, const float *__restrict__ g2,
              const float *__restrict__ be2, const float *__restrict__ W3,
              const float *__restrict__ b3) {
    const int bs = blockIdx.x;
    const int b = bs / NSAMP, s = bs % NSAMP;
    __shared__ int   s_cnt;
    __shared__ int   s_cand[MAXC];
    __shared__ float s_score[MAXC];
    if (threadIdx.x == 0) s_cnt = 0;
    __syncthreads();

    const float bestA = unflipf(g_bestu[bs]);
    const float thr = bestA - DELTA;
    const float *sc = g_scores + bs * E_CNT;
    for (int e = threadIdx.x; e < E_CNT; e += blockDim.x) {
        if (sc[e] >= thr) {
            int i = atomicAdd(&s_cnt, 1);
            if (i < MAXC) s_cand[i] = e;
        }
    }
    __syncthreads();
    int n = min(s_cnt, MAXC);

    const int warp = threadIdx.x >> 5, lane = threadIdx.x & 31;
    for (int i = warp; i < n; i += 8) {
        float v = exact_score(s_cand[i], b, s, W2, b1, g1, be1, b2, g2, be2, W3, b3, lane);
        if (lane == 0) s_score[i] = v;
    }
    __syncthreads();
    if (threadIdx.x == 0) {
        float best = -__int_as_float(0x7f800000);
        int beste = 0x7FFFFFFF;
        for (int i = 0; i < n; ++i) {
            if (s_score[i] > best || (s_score[i] == best && s_cand[i] < beste)) {
                best = s_score[i];
                beste = s_cand[i];
            }
        }
        g_winner[bs] = beste;
    }
}

// ---------------------------------------------------------------------------
// Kernel 4: scatter winners
// ---------------------------------------------------------------------------
__global__ void finalize_kernel(float *out) {
    int t = threadIdx.x;
    if (t >= BATCH * NSAMP) return;
    int e = g_winner[t];
    int b = t / NSAMP;
    int r, c;
    decode_edge(e, r, c);
    out[b * NN * NN + r * NN + c] = 1.0f;
}

// ---------------------------------------------------------------------------
extern "C" void kernel_launch(void *const *d_in, const int *in_sizes, int n_in,
                              void *d_out, int out_size) {
    const float *nodes = (const float *)d_in[0];
    const float *W1    = (const float *)d_in[1];
    const float *b1    = (const float *)d_in[2];
    const float *g1    = (const float *)d_in[3];
    const float *be1   = (const float *)d_in[4];
    const float *W2    = (const float *)d_in[5];
    const float *b2    = (const float *)d_in[6];
    const float *g2    = (const float *)d_in[7];
    const float *be2   = (const float *)d_in[8];
    const float *W3    = (const float *)d_in[9];
    const float *b3    = (const float *)d_in[10];

    cudaFuncSetAttribute(main_mma, cudaFuncAttributeMaxDynamicSharedMemorySize, SMEM_MAIN);

    init_kernel<<<1024, 256>>>((float4 *)d_out);
    precompute_kernel<<<BATCH * NN / 8, FEAT>>>(nodes, W1);
    main_mma<<<dim3(NTILE, BATCH), 128, SMEM_MAIN>>>(
        b1, g1, be1, W2, b2, g2, be2, W3, b3);
    refine_kernel<<<BATCH * NSAMP, 256>>>(W2, b1, g1, be1, b2, g2, be2, W3, b3);
    finalize_kernel<<<1, 32>>>((float *)d_out);
}